// round 7
// baseline (speedup 1.0000x reference)
#include <cuda_runtime.h>
#include <math.h>

#define NB     4096
#define ND     4096
#define NCLS   10
#define NSUB   8            // sub-chunks per class in the sorted pass
#define MAXLEN 512          // ceil(NB / NSUB) upper bound on rows per sub-chunk
#define CEB    16           // blocks in k_ce (256 rows each)

// Scratch (no allocations allowed -> __device__ globals)
__device__ float  g_r[NB];              // 1/||g_i - min_i||
__device__ float  g_mn[NB];             // row min
__device__ int    g_cls[NB];            // argmax class
__device__ int    g_bpos[NB];           // within-(ce-block,class) rank
__device__ int    g_bcnt[CEB][NCLS];    // per-ce-block class counts (plain stores)
__device__ double g_cepart[CEB];        // per-ce-block CE partials (plain stores)
__device__ int    g_order[NB];          // rows sorted by class
__device__ float  g_rs[NB];             // r gathered into sorted order
__device__ int    g_off[NCLS + 1];      // class offsets
__device__ double g_tc[NCLS];           // sum over class of mn_i * r_i
__device__ double g_ce;
__device__ double g_s2part[NCLS * 4];
__device__ float  g_part[NCLS][NSUB][ND];  // per-(class,sub) column partials
__device__ unsigned int g_tick1;        // rowstats last-block ticket
__device__ unsigned int g_tick2;        // norm2 last-block ticket

// --------------------------------------- CE + argmax + per-block class counts
// 16 blocks x 256. No global atomics, no pre-zeroing (graph-replay safe).
__global__ void __launch_bounds__(256) k_ce(
    const float* __restrict__ outputs, const int* __restrict__ y) {
    __shared__ int    cnt[NCLS];
    __shared__ double ced[8];
    int tid = threadIdx.x;
    if (tid < NCLS) cnt[tid] = 0;
    if (blockIdx.x == 0 && tid == 0) g_tick1 = 0u;  // ticket for k_rowstats tail
    __syncthreads();

    int row = blockIdx.x * 256 + tid;
    const float* o = outputs + row * NCLS;
    float vals[NCLS];
    float mx = o[0]; int am = 0;
    vals[0] = mx;
#pragma unroll
    for (int c = 1; c < NCLS; c++) {
        float v = o[c]; vals[c] = v;
        if (v > mx) { mx = v; am = c; }   // strict > == first max (jnp.argmax)
    }
    float e = 0.f;
#pragma unroll
    for (int c = 0; c < NCLS; c++) e += __expf(vals[c] - mx);
    double local = (double)mx + log((double)e) - (double)vals[y[row]];

    g_cls[row]  = am;
    g_bpos[row] = atomicAdd(&cnt[am], 1);  // smem atomic (block-local)

#pragma unroll
    for (int off = 16; off; off >>= 1)
        local += __shfl_xor_sync(0xffffffffu, local, off);
    if ((tid & 31) == 0) ced[tid >> 5] = local;
    __syncthreads();
    if (tid < NCLS) g_bcnt[blockIdx.x][tid] = cnt[tid];
    if (tid == 0) {
        double s = 0.0;
        for (int i = 0; i < 8; i++) s += ced[i];
        g_cepart[blockIdx.x] = s;
    }
}

// ---------------- per-row min / sum / sumsq ; last block runs scan + scatter
__global__ void __launch_bounds__(128) k_rowstats(const float* __restrict__ grad) {
    int row = blockIdx.x;
    int tid = threadIdx.x;
    const float4* gp = (const float4*)grad + (size_t)row * (ND / 4);

    float mn = 3.0e38f, sum = 0.f, sq = 0.f;
#pragma unroll
    for (int j = 0; j < 8; j++) {
        float4 v = gp[j * 128 + tid];
        mn  = fminf(mn, fminf(fminf(v.x, v.y), fminf(v.z, v.w)));
        sum += (v.x + v.y) + (v.z + v.w);
        sq  += (v.x * v.x + v.y * v.y) + (v.z * v.z + v.w * v.w);
    }
#pragma unroll
    for (int o = 16; o; o >>= 1) {
        mn   = fminf(mn, __shfl_xor_sync(0xffffffffu, mn, o));
        sum += __shfl_xor_sync(0xffffffffu, sum, o);
        sq  += __shfl_xor_sync(0xffffffffu, sq, o);
    }
    __shared__ float smn[4], ssum[4], ssq[4];
    int w = tid >> 5;
    if ((tid & 31) == 0) { smn[w] = mn; ssum[w] = sum; ssq[w] = sq; }
    __syncthreads();
    if (tid == 0) {
        mn = fminf(fminf(smn[0], smn[1]), fminf(smn[2], smn[3]));
        double s = (double)ssum[0] + ssum[1] + ssum[2] + ssum[3];
        double q = (double)ssq[0] + ssq[1] + ssq[2] + ssq[3];
        double mnd = (double)mn;
        // sum of (g-min)^2 ; the (max-min) scale cancels in cosine similarity
        double var = q - 2.0 * mnd * s + (double)ND * mnd * mnd;
        g_r[row]  = (float)(1.0 / sqrt(var));
        g_mn[row] = mn;
    }

    // ---- last-block tail: offsets scan + scatter + t_c (replaces 2 kernels)
    __shared__ unsigned int isLast;
    __threadfence();
    if (tid == 0) isLast = (atomicAdd(&g_tick1, 1u) == NB - 1) ? 1u : 0u;
    __syncthreads();
    if (!isLast) return;

    __shared__ int clsoff[NCLS];
    __shared__ int base[CEB][NCLS];
    __shared__ double tc[NCLS];
    if (tid < NCLS) tc[tid] = 0.0;
    if (tid == 0) {
        int acc = 0;
        for (int c = 0; c < NCLS; c++) {
            clsoff[c] = acc;
            int run = 0;
            for (int b = 0; b < CEB; b++) { base[b][c] = run; run += g_bcnt[b][c]; }
            acc += run;
            g_off[c] = clsoff[c];
        }
        g_off[NCLS] = acc;      // == NB
        double ce = 0.0;
        for (int b = 0; b < CEB; b++) ce += g_cepart[b];
        g_ce = ce;
        g_tick2 = 0u;           // ticket for k_norm2 tail
    }
    __syncthreads();
    for (int r = tid; r < NB; r += 128) {
        int c = g_cls[r];
        int p = clsoff[c] + base[r >> 8][c] + g_bpos[r];
        float rv = g_r[r];
        g_order[p] = r;
        g_rs[p]    = rv;
        atomicAdd(&tc[c], (double)g_mn[r] * (double)rv);
    }
    __syncthreads();
    if (tid < NCLS) g_tc[tid] = tc[tid];
}

// ---------------------------- class column sums over class-sorted rows
// grid (4 stripes, NCLS, NSUB). One class per block -> 1 FFMA per element.
__global__ void __launch_bounds__(256) k_classsum(const float* __restrict__ grad) {
    int col = blockIdx.x * 1024 + threadIdx.x * 4;
    int c   = blockIdx.y;
    int s   = blockIdx.z;
    int beg = g_off[c], end = g_off[c + 1];
    int n   = end - beg;
    int len = (n + NSUB - 1) / NSUB;
    int lo  = beg + s * len;
    int hi  = min(lo + len, end);
    int cnt = max(hi - lo, 0);

    __shared__ int   sidx[MAXLEN];
    __shared__ float sr[MAXLEN];
    for (int i = threadIdx.x; i < cnt; i += 256) {
        sidx[i] = g_order[lo + i];
        sr[i]   = g_rs[lo + i];
    }
    __syncthreads();

    float4 acc = make_float4(0.f, 0.f, 0.f, 0.f);
    int i = 0;
    for (; i + 4 <= cnt; i += 4) {
        const float4 v0 = *(const float4*)(grad + (size_t)sidx[i + 0] * ND + col);
        const float4 v1 = *(const float4*)(grad + (size_t)sidx[i + 1] * ND + col);
        const float4 v2 = *(const float4*)(grad + (size_t)sidx[i + 2] * ND + col);
        const float4 v3 = *(const float4*)(grad + (size_t)sidx[i + 3] * ND + col);
        float r0 = sr[i + 0], r1 = sr[i + 1], r2 = sr[i + 2], r3 = sr[i + 3];
        acc.x = fmaf(r0, v0.x, acc.x); acc.y = fmaf(r0, v0.y, acc.y);
        acc.z = fmaf(r0, v0.z, acc.z); acc.w = fmaf(r0, v0.w, acc.w);
        acc.x = fmaf(r1, v1.x, acc.x); acc.y = fmaf(r1, v1.y, acc.y);
        acc.z = fmaf(r1, v1.z, acc.z); acc.w = fmaf(r1, v1.w, acc.w);
        acc.x = fmaf(r2, v2.x, acc.x); acc.y = fmaf(r2, v2.y, acc.y);
        acc.z = fmaf(r2, v2.z, acc.z); acc.w = fmaf(r2, v2.w, acc.w);
        acc.x = fmaf(r3, v3.x, acc.x); acc.y = fmaf(r3, v3.y, acc.y);
        acc.z = fmaf(r3, v3.z, acc.z); acc.w = fmaf(r3, v3.w, acc.w);
    }
    for (; i < cnt; i++) {
        const float4 v = *(const float4*)(grad + (size_t)sidx[i] * ND + col);
        float r = sr[i];
        acc.x = fmaf(r, v.x, acc.x); acc.y = fmaf(r, v.y, acc.y);
        acc.z = fmaf(r, v.z, acc.z); acc.w = fmaf(r, v.w, acc.w);
    }
    // unconditional write covers empty classes/subs (no pre-zeroing needed)
    *(float4*)&g_part[c][s][col] = acc;
}

// --------------- ||S_c||^2 with mean-shift (t_c) ; last block emits the loss
__global__ void __launch_bounds__(256) k_norm2(float* __restrict__ out) {
    int c   = blockIdx.x;
    int col = blockIdx.y * 1024 + threadIdx.x * 4;
    double tcv = g_tc[c];
    float4 s = make_float4(0.f, 0.f, 0.f, 0.f);
#pragma unroll
    for (int sub = 0; sub < NSUB; sub++) {
        float4 v = *(const float4*)&g_part[c][sub][col];
        s.x += v.x; s.y += v.y; s.z += v.z; s.w += v.w;
    }
    double a = (double)s.x - tcv, b = (double)s.y - tcv;
    double d = (double)s.z - tcv, e = (double)s.w - tcv;
    double local = a * a + b * b + d * d + e * e;
#pragma unroll
    for (int o = 16; o; o >>= 1)
        local += __shfl_xor_sync(0xffffffffu, local, o);
    __shared__ double sd[8];
    int tid = threadIdx.x;
    if ((tid & 31) == 0) sd[tid >> 5] = local;
    __syncthreads();
    int bid = blockIdx.x * 4 + blockIdx.y;
    if (tid == 0) {
        double t = 0.0;
        for (int i = 0; i < 8; i++) t += sd[i];
        g_s2part[bid] = t;
    }
    __shared__ unsigned int isLast;
    __threadfence();
    if (tid == 0) isLast = (atomicAdd(&g_tick2, 1u) == NCLS * 4 - 1) ? 1u : 0u;
    __syncthreads();
    if (isLast && tid == 0) {
        double s2 = 0.0;
        for (int i = 0; i < NCLS * 4; i++) s2 += g_s2part[i];
        double P = 0.0;
        for (int k = 0; k < NCLS; k++) {
            double nc = (double)(g_off[k + 1] - g_off[k]);
            P += 0.5 * nc * (nc - 1.0);
        }
        double simsum = 0.5 * (s2 - (double)NB);  // sum of sim over i<j same-class
        double xloss  = (P - simsum) / (double)NB;
        out[0] = (float)(g_ce / (double)NB + xloss);
    }
}

extern "C" void kernel_launch(void* const* d_in, const int* in_sizes, int n_in,
                              void* d_out, int out_size) {
    (void)out_size;
    const float* outputs = nullptr;
    const float* grad    = nullptr;
    const int*   y       = nullptr;
    for (int i = 0; i < n_in; i++) {
        if      (in_sizes[i] == NB * ND)   grad    = (const float*)d_in[i];
        else if (in_sizes[i] == NB * NCLS) outputs = (const float*)d_in[i];
        else if (in_sizes[i] == NB)        y       = (const int*)d_in[i];
    }
    float* out = (float*)d_out;

    k_ce<<<CEB, 256>>>(outputs, y);
    k_rowstats<<<NB, 128>>>(grad);
    k_classsum<<<dim3(4, NCLS, NSUB), 256>>>(grad);
    k_norm2<<<dim3(NCLS, 4), 256>>>(out);
}

// round 9
// speedup vs baseline: 1.9152x; 1.9152x over previous
#include <cuda_runtime.h>
#include <math.h>

#define NB     4096
#define ND     4096
#define NCLS   10
#define NSUB   8            // sub-chunks per class in the sorted pass
#define MAXLEN 512          // ceil(NB / NSUB) upper bound on rows per sub-chunk
#define CEB    16           // rowstats blocks that also do CE (256 rows each)

// Scratch (no allocations allowed -> __device__ globals)
__device__ float  g_r[NB];              // 1/||g_i - min_i||
__device__ float  g_mn[NB];             // row min
__device__ int    g_cls[NB];            // argmax class
__device__ int    g_bpos[NB];           // within-(ce-block,class) rank
__device__ int    g_bcnt[CEB][NCLS];    // per-ce-block class counts (plain stores)
__device__ double g_cepart[CEB];        // per-ce-block CE partials (plain stores)
__device__ int    g_order[NB];          // rows sorted by class
__device__ float  g_rs[NB];             // r gathered into sorted order
__device__ int    g_off[NCLS + 1];      // class offsets
__device__ double g_tc[NCLS];           // sum over class of mn_i * r_i
__device__ float  g_part[NCLS][NSUB][ND];  // per-(class,sub) column partials

// ------------- pass 1: per-row min / sum / sumsq ; blocks 0..15 also do CE
__global__ void __launch_bounds__(128) k_rowstats(
    const float* __restrict__ grad, const float* __restrict__ outputs,
    const int* __restrict__ y) {
    int row = blockIdx.x;
    int tid = threadIdx.x;
    const float4* gp = (const float4*)grad + (size_t)row * (ND / 4);

    float mn = 3.0e38f, sum = 0.f, sq = 0.f;
#pragma unroll
    for (int j = 0; j < 8; j++) {
        float4 v = gp[j * 128 + tid];
        mn  = fminf(mn, fminf(fminf(v.x, v.y), fminf(v.z, v.w)));
        sum += (v.x + v.y) + (v.z + v.w);
        sq  += (v.x * v.x + v.y * v.y) + (v.z * v.z + v.w * v.w);
    }
#pragma unroll
    for (int o = 16; o; o >>= 1) {
        mn   = fminf(mn, __shfl_xor_sync(0xffffffffu, mn, o));
        sum += __shfl_xor_sync(0xffffffffu, sum, o);
        sq  += __shfl_xor_sync(0xffffffffu, sq, o);
    }
    __shared__ float smn[4], ssum[4], ssq[4];
    int w = tid >> 5;
    if ((tid & 31) == 0) { smn[w] = mn; ssum[w] = sum; ssq[w] = sq; }
    __syncthreads();
    if (tid == 0) {
        mn = fminf(fminf(smn[0], smn[1]), fminf(smn[2], smn[3]));
        double s = (double)ssum[0] + ssum[1] + ssum[2] + ssum[3];
        double q = (double)ssq[0] + ssq[1] + ssq[2] + ssq[3];
        double mnd = (double)mn;
        // sum of (g-min)^2 ; the (max-min) scale cancels in cosine similarity
        double var = q - 2.0 * mnd * s + (double)ND * mnd * mnd;
        g_r[row]  = (float)(1.0 / sqrt(var));
        g_mn[row] = mn;
    }

    // ---- CE / argmax / per-block class counts (blocks 0..15, 256 rows each)
    if (blockIdx.x < CEB) {
        __shared__ int    cnt[NCLS];
        __shared__ double ced[4];
        if (tid < NCLS) cnt[tid] = 0;
        __syncthreads();
        double local = 0.0;
#pragma unroll
        for (int k = 0; k < 2; k++) {
            int rr = blockIdx.x * 256 + k * 128 + tid;
            const float* o = outputs + rr * NCLS;
            float vals[NCLS];
            float mx = o[0]; int am = 0;
            vals[0] = mx;
#pragma unroll
            for (int c = 1; c < NCLS; c++) {
                float v = o[c]; vals[c] = v;
                if (v > mx) { mx = v; am = c; }  // strict > == first max (jnp.argmax)
            }
            float e = 0.f;
#pragma unroll
            for (int c = 0; c < NCLS; c++) e += __expf(vals[c] - mx);
            local += (double)mx + log((double)e) - (double)vals[y[rr]];
            g_cls[rr]  = am;
            g_bpos[rr] = atomicAdd(&cnt[am], 1);   // smem atomic (block-local)
        }
#pragma unroll
        for (int o = 16; o; o >>= 1)
            local += __shfl_xor_sync(0xffffffffu, local, o);
        if ((tid & 31) == 0) ced[tid >> 5] = local;
        __syncthreads();
        if (tid < NCLS) g_bcnt[blockIdx.x][tid] = cnt[tid];
        if (tid == 0)
            g_cepart[blockIdx.x] = ced[0] + ced[1] + ced[2] + ced[3];
    }
}

// -------- prep (1 block): scan + scatter + t_c + CE total + out base value
__global__ void __launch_bounds__(256) k_prep(float* __restrict__ out) {
    int tid = threadIdx.x;
    __shared__ int clsoff[NCLS];
    __shared__ int base[CEB][NCLS];
    __shared__ double tc[NCLS];
    if (tid < NCLS) tc[tid] = 0.0;
    if (tid == 0) {
        int acc = 0;
        double P = 0.0;
        for (int c = 0; c < NCLS; c++) {
            clsoff[c] = acc;
            g_off[c]  = acc;
            int run = 0;
            for (int b = 0; b < CEB; b++) { base[b][c] = run; run += g_bcnt[b][c]; }
            acc += run;
            P += 0.5 * (double)run * (double)(run - 1);
        }
        g_off[NCLS] = acc;        // == NB
        double ce = 0.0;
        for (int b = 0; b < CEB; b++) ce += g_cepart[b];
        // loss = ce/B + P/B + 0.5 - s2/(2B); norm2 blocks subtract their s2 share
        out[0] = (float)(ce / (double)NB + P / (double)NB + 0.5);
    }
    __syncthreads();
    for (int r = tid; r < NB; r += 256) {
        int c = g_cls[r];
        int p = clsoff[c] + base[r >> 8][c] + g_bpos[r];
        float rv = g_r[r];
        g_order[p] = r;
        g_rs[p]    = rv;
        atomicAdd(&tc[c], (double)g_mn[r] * (double)rv);
    }
    __syncthreads();
    if (tid < NCLS) g_tc[tid] = tc[tid];
}

// ---------------------------- class column sums over class-sorted rows
// grid (4 stripes, NCLS, NSUB). One class per block -> 1 FFMA per element.
__global__ void __launch_bounds__(256) k_classsum(const float* __restrict__ grad) {
    int col = blockIdx.x * 1024 + threadIdx.x * 4;
    int c   = blockIdx.y;
    int s   = blockIdx.z;
    int beg = g_off[c], end = g_off[c + 1];
    int n   = end - beg;
    int len = (n + NSUB - 1) / NSUB;
    int lo  = beg + s * len;
    int hi  = min(lo + len, end);
    int cnt = max(hi - lo, 0);

    __shared__ int   sidx[MAXLEN];
    __shared__ float sr[MAXLEN];
    for (int i = threadIdx.x; i < cnt; i += 256) {
        sidx[i] = g_order[lo + i];
        sr[i]   = g_rs[lo + i];
    }
    __syncthreads();

    float4 acc = make_float4(0.f, 0.f, 0.f, 0.f);
    int i = 0;
    for (; i + 4 <= cnt; i += 4) {
        const float4 v0 = *(const float4*)(grad + (size_t)sidx[i + 0] * ND + col);
        const float4 v1 = *(const float4*)(grad + (size_t)sidx[i + 1] * ND + col);
        const float4 v2 = *(const float4*)(grad + (size_t)sidx[i + 2] * ND + col);
        const float4 v3 = *(const float4*)(grad + (size_t)sidx[i + 3] * ND + col);
        float r0 = sr[i + 0], r1 = sr[i + 1], r2 = sr[i + 2], r3 = sr[i + 3];
        acc.x = fmaf(r0, v0.x, acc.x); acc.y = fmaf(r0, v0.y, acc.y);
        acc.z = fmaf(r0, v0.z, acc.z); acc.w = fmaf(r0, v0.w, acc.w);
        acc.x = fmaf(r1, v1.x, acc.x); acc.y = fmaf(r1, v1.y, acc.y);
        acc.z = fmaf(r1, v1.z, acc.z); acc.w = fmaf(r1, v1.w, acc.w);
        acc.x = fmaf(r2, v2.x, acc.x); acc.y = fmaf(r2, v2.y, acc.y);
        acc.z = fmaf(r2, v2.z, acc.z); acc.w = fmaf(r2, v2.w, acc.w);
        acc.x = fmaf(r3, v3.x, acc.x); acc.y = fmaf(r3, v3.y, acc.y);
        acc.z = fmaf(r3, v3.z, acc.z); acc.w = fmaf(r3, v3.w, acc.w);
    }
    for (; i < cnt; i++) {
        const float4 v = *(const float4*)(grad + (size_t)sidx[i] * ND + col);
        float r = sr[i];
        acc.x = fmaf(r, v.x, acc.x); acc.y = fmaf(r, v.y, acc.y);
        acc.z = fmaf(r, v.z, acc.z); acc.w = fmaf(r, v.w, acc.w);
    }
    // unconditional write covers empty classes/subs (no pre-zeroing needed)
    *(float4*)&g_part[c][s][col] = acc;
}

// ---- ||S_c||^2 with mean-shift (t_c); each block folds its share into out
// grid (NCLS, 16) x 64 threads: class c, 256-column segment, thread owns 4 cols.
__global__ void __launch_bounds__(64) k_norm2(float* __restrict__ out) {
    int c   = blockIdx.x;
    int col = blockIdx.y * 256 + threadIdx.x * 4;
    double tcv = g_tc[c];
    float4 s = make_float4(0.f, 0.f, 0.f, 0.f);
#pragma unroll
    for (int sub = 0; sub < NSUB; sub++) {
        float4 v = *(const float4*)&g_part[c][sub][col];
        s.x += v.x; s.y += v.y; s.z += v.z; s.w += v.w;
    }
    double a = (double)s.x - tcv, b = (double)s.y - tcv;
    double d = (double)s.z - tcv, e = (double)s.w - tcv;
    double local = a * a + b * b + d * d + e * e;
#pragma unroll
    for (int o = 16; o; o >>= 1)
        local += __shfl_xor_sync(0xffffffffu, local, o);
    __shared__ double sd[2];
    int tid = threadIdx.x;
    if ((tid & 31) == 0) sd[tid >> 5] = local;
    __syncthreads();
    if (tid == 0) {
        double t = sd[0] + sd[1];
        atomicAdd(out, (float)(-t / (2.0 * (double)NB)));
    }
}

extern "C" void kernel_launch(void* const* d_in, const int* in_sizes, int n_in,
                              void* d_out, int out_size) {
    (void)out_size;
    const float* outputs = nullptr;
    const float* grad    = nullptr;
    const int*   y       = nullptr;
    for (int i = 0; i < n_in; i++) {
        if      (in_sizes[i] == NB * ND)   grad    = (const float*)d_in[i];
        else if (in_sizes[i] == NB * NCLS) outputs = (const float*)d_in[i];
        else if (in_sizes[i] == NB)        y       = (const int*)d_in[i];
    }
    float* out = (float*)d_out;

    k_rowstats<<<NB, 128>>>(grad, outputs, y);
    k_prep<<<1, 256>>>(out);
    k_classsum<<<dim3(4, NCLS, NSUB), 256>>>(grad);
    k_norm2<<<dim3(NCLS, 16), 64>>>(out);
}

// round 10
// speedup vs baseline: 3.3630x; 1.7560x over previous
#include <cuda_runtime.h>
#include <math.h>

#define NB     4096
#define ND     4096
#define NCLS   10
#define NSUB   16           // sub-chunks per class in the sorted pass
#define MAXLEN 256          // ceil(NB / NSUB) worst case (whole batch one class)
#define CEB    16           // blocks in k_ce (256 rows each)

// Scratch (no allocations allowed -> __device__ globals)
__device__ float  g_r[NB];              // 1/||g_i - min_i||
__device__ int    g_cls[NB];            // argmax class
__device__ int    g_bpos[NB];           // within-(ce-block,class) rank
__device__ int    g_bcnt[CEB][NCLS];    // per-ce-block class counts (plain stores)
__device__ double g_cepart[CEB];        // per-ce-block CE partials (plain stores)
__device__ double g_tc[NCLS];           // sum over class of mn_i * r_i
__device__ float  g_part[NCLS][NSUB][ND];  // per-(class,sub) column partials

// --------------------- CE + argmax + per-block class counts; zeroes g_tc
__global__ void __launch_bounds__(256) k_ce(
    const float* __restrict__ outputs, const int* __restrict__ y) {
    __shared__ int    cnt[NCLS];
    __shared__ double ced[8];
    int tid = threadIdx.x;
    if (tid < NCLS) cnt[tid] = 0;
    if (blockIdx.x == 0 && tid < NCLS) g_tc[tid] = 0.0;  // replay-safe re-zero
    __syncthreads();

    int row = blockIdx.x * 256 + tid;
    const float* o = outputs + row * NCLS;
    float vals[NCLS];
    float mx = o[0]; int am = 0;
    vals[0] = mx;
#pragma unroll
    for (int c = 1; c < NCLS; c++) {
        float v = o[c]; vals[c] = v;
        if (v > mx) { mx = v; am = c; }   // strict > == first max (jnp.argmax)
    }
    float e = 0.f;
#pragma unroll
    for (int c = 0; c < NCLS; c++) e += __expf(vals[c] - mx);
    double local = (double)mx + log((double)e) - (double)vals[y[row]];

    g_cls[row]  = am;
    g_bpos[row] = atomicAdd(&cnt[am], 1);   // smem atomic (block-local)

#pragma unroll
    for (int off = 16; off; off >>= 1)
        local += __shfl_xor_sync(0xffffffffu, local, off);
    if ((tid & 31) == 0) ced[tid >> 5] = local;
    __syncthreads();
    if (tid < NCLS) g_bcnt[blockIdx.x][tid] = cnt[tid];
    if (tid == 0) {
        double s = 0.0;
        for (int i = 0; i < 8; i++) s += ced[i];
        g_cepart[blockIdx.x] = s;
    }
}

// ---------------- pass 1: per-row min / sum / sumsq (lean streaming kernel)
__global__ void __launch_bounds__(128) k_rowstats(const float* __restrict__ grad) {
    int row = blockIdx.x;
    int tid = threadIdx.x;
    const float4* gp = (const float4*)grad + (size_t)row * (ND / 4);

    float mn = 3.0e38f, sum = 0.f, sq = 0.f;
#pragma unroll
    for (int j = 0; j < 8; j++) {
        float4 v = gp[j * 128 + tid];
        mn  = fminf(mn, fminf(fminf(v.x, v.y), fminf(v.z, v.w)));
        sum += (v.x + v.y) + (v.z + v.w);
        sq  += (v.x * v.x + v.y * v.y) + (v.z * v.z + v.w * v.w);
    }
#pragma unroll
    for (int o = 16; o; o >>= 1) {
        mn   = fminf(mn, __shfl_xor_sync(0xffffffffu, mn, o));
        sum += __shfl_xor_sync(0xffffffffu, sum, o);
        sq  += __shfl_xor_sync(0xffffffffu, sq, o);
    }
    __shared__ float smn[4], ssum[4], ssq[4];
    int w = tid >> 5;
    if ((tid & 31) == 0) { smn[w] = mn; ssum[w] = sum; ssq[w] = sq; }
    __syncthreads();
    if (tid == 0) {
        mn = fminf(fminf(smn[0], smn[1]), fminf(smn[2], smn[3]));
        double s = (double)ssum[0] + ssum[1] + ssum[2] + ssum[3];
        double q = (double)ssq[0] + ssq[1] + ssq[2] + ssq[3];
        double mnd = (double)mn;
        // sum of (g-min)^2 ; the (max-min) scale cancels in cosine similarity
        double var = q - 2.0 * mnd * s + (double)ND * mnd * mnd;
        float rinv = (float)(1.0 / sqrt(var));
        g_r[row] = rinv;
        // t_c accumulation: 4096 double atomics over 10 addrs, hidden by stream
        atomicAdd(&g_tc[g_cls[row]], mnd * (double)rinv);
    }
}

// ------------- pass 2: class column sums; each block builds its own row list
// grid (4 stripes, NCLS, NSUB). One class per block -> 1 FFMA per element.
__global__ void __launch_bounds__(256) k_classsum(
    const float* __restrict__ grad, float* __restrict__ out) {
    int tid = threadIdx.x;
    int c   = blockIdx.y;
    int s   = blockIdx.z;
    __shared__ int   base[CEB + 1];
    __shared__ int   sidx[MAXLEN];
    __shared__ float sr[MAXLEN];
    if (tid == 0) {
        int acc = 0;
        for (int b = 0; b < CEB; b++) { base[b] = acc; acc += g_bcnt[b][c]; }
        base[CEB] = acc;   // n_c
    }
    __syncthreads();
    int n   = base[CEB];
    int len = (n + NSUB - 1) / NSUB;
    int lo  = s * len;
    int hi  = min(lo + len, n);
    int cnt = max(hi - lo, 0);

    // gather this block's row slice by scanning class ids (L2-broadcast, 16 KB)
    for (int r = tid; r < NB; r += 256) {
        if (g_cls[r] == c) {
            int p = base[r >> 8] + g_bpos[r];
            if (p >= lo && p < hi) {
                int q = p - lo;
                sidx[q] = r;
                sr[q]   = g_r[r];
            }
        }
    }
    // one designated block writes the loss base (before k_norm2 launches)
    if (blockIdx.x == 0 && c == 0 && s == 0 && tid == 0) {
        double ce = 0.0;
        for (int b = 0; b < CEB; b++) ce += g_cepart[b];
        double P = 0.0;
        for (int k = 0; k < NCLS; k++) {
            int nc = 0;
            for (int b = 0; b < CEB; b++) nc += g_bcnt[b][k];
            P += 0.5 * (double)nc * (double)(nc - 1);
        }
        // loss = ce/B + P/B + 0.5 - s2/(2B); norm2 blocks subtract s2 shares
        out[0] = (float)(ce / (double)NB + P / (double)NB + 0.5);
    }
    __syncthreads();

    int col = blockIdx.x * 1024 + tid * 4;
    float4 acc = make_float4(0.f, 0.f, 0.f, 0.f);
    int i = 0;
    for (; i + 4 <= cnt; i += 4) {
        const float4 v0 = *(const float4*)(grad + (size_t)sidx[i + 0] * ND + col);
        const float4 v1 = *(const float4*)(grad + (size_t)sidx[i + 1] * ND + col);
        const float4 v2 = *(const float4*)(grad + (size_t)sidx[i + 2] * ND + col);
        const float4 v3 = *(const float4*)(grad + (size_t)sidx[i + 3] * ND + col);
        float r0 = sr[i + 0], r1 = sr[i + 1], r2 = sr[i + 2], r3 = sr[i + 3];
        acc.x = fmaf(r0, v0.x, acc.x); acc.y = fmaf(r0, v0.y, acc.y);
        acc.z = fmaf(r0, v0.z, acc.z); acc.w = fmaf(r0, v0.w, acc.w);
        acc.x = fmaf(r1, v1.x, acc.x); acc.y = fmaf(r1, v1.y, acc.y);
        acc.z = fmaf(r1, v1.z, acc.z); acc.w = fmaf(r1, v1.w, acc.w);
        acc.x = fmaf(r2, v2.x, acc.x); acc.y = fmaf(r2, v2.y, acc.y);
        acc.z = fmaf(r2, v2.z, acc.z); acc.w = fmaf(r2, v2.w, acc.w);
        acc.x = fmaf(r3, v3.x, acc.x); acc.y = fmaf(r3, v3.y, acc.y);
        acc.z = fmaf(r3, v3.z, acc.z); acc.w = fmaf(r3, v3.w, acc.w);
    }
    for (; i < cnt; i++) {
        const float4 v = *(const float4*)(grad + (size_t)sidx[i] * ND + col);
        float r = sr[i];
        acc.x = fmaf(r, v.x, acc.x); acc.y = fmaf(r, v.y, acc.y);
        acc.z = fmaf(r, v.z, acc.z); acc.w = fmaf(r, v.w, acc.w);
    }
    // unconditional write covers empty classes/subs (no pre-zeroing needed)
    *(float4*)&g_part[c][s][col] = acc;
}

// ---- ||S_c||^2 with mean-shift (t_c); blocks fold -s2/(2B) shares into out
// grid (NCLS, 16) x 256: block covers 256 cols; subs split across 4 thread grps.
__global__ void __launch_bounds__(256) k_norm2(float* __restrict__ out) {
    int tid = threadIdx.x;
    int c   = blockIdx.x;
    int c4  = tid & 63;              // which float4-column (64 per block)
    int grp = tid >> 6;              // 4 groups x 4 subs each
    int col = blockIdx.y * 256 + c4 * 4;

    float4 p = make_float4(0.f, 0.f, 0.f, 0.f);
#pragma unroll
    for (int k = 0; k < 4; k++) {
        float4 v = *(const float4*)&g_part[c][grp * 4 + k][col];
        p.x += v.x; p.y += v.y; p.z += v.z; p.w += v.w;
    }
    __shared__ float4 sp[4][64];
    sp[grp][c4] = p;
    __syncthreads();

    __shared__ double sd[2];
    if (tid < 64) {
        float4 a = sp[0][tid], b = sp[1][tid], d = sp[2][tid], e = sp[3][tid];
        double tcv = g_tc[c];
        double x = (double)(a.x + b.x + d.x + e.x) - tcv;
        double yv = (double)(a.y + b.y + d.y + e.y) - tcv;
        double z = (double)(a.z + b.z + d.z + e.z) - tcv;
        double w = (double)(a.w + b.w + d.w + e.w) - tcv;
        double local = x * x + yv * yv + z * z + w * w;
#pragma unroll
        for (int o = 16; o; o >>= 1)
            local += __shfl_xor_sync(0xffffffffu, local, o);
        if ((tid & 31) == 0) sd[tid >> 5] = local;
    }
    __syncthreads();
    if (tid == 0)
        atomicAdd(out, (float)(-(sd[0] + sd[1]) / (2.0 * (double)NB)));
}

extern "C" void kernel_launch(void* const* d_in, const int* in_sizes, int n_in,
                              void* d_out, int out_size) {
    (void)out_size;
    const float* outputs = nullptr;
    const float* grad    = nullptr;
    const int*   y       = nullptr;
    for (int i = 0; i < n_in; i++) {
        if      (in_sizes[i] == NB * ND)   grad    = (const float*)d_in[i];
        else if (in_sizes[i] == NB * NCLS) outputs = (const float*)d_in[i];
        else if (in_sizes[i] == NB)        y       = (const int*)d_in[i];
    }
    float* out = (float*)d_out;

    k_ce<<<CEB, 256>>>(outputs, y);
    k_rowstats<<<NB, 128>>>(grad);
    k_classsum<<<dim3(4, NCLS, NSUB), 256>>>(grad, out);
    k_norm2<<<dim3(NCLS, 16), 256>>>(out);
}